// round 5
// baseline (speedup 1.0000x reference)
#include <cuda_runtime.h>
#include <stdint.h>

// VTM downsampler — fp32, packed f32x2 vertical filters + u8-saturating epilogue.
// Exact: all intermediates are integers < 2^24 (fp32-exact); clip(floor((s+8192)/2^14),0,255)
// == cvt.rzi.sat.u8 of (s+8192)*2^-14  (trunc==floor for v>=0; v<0 clamps to 0 either way).
//
// integer = i>>2, frac = 4*(i&3) -> FILTER rows {0,4,8,12}, taps k=3..8.
// Phase 0 = delta (128*center); phase 2 symmetric.

#define IH 1080
#define IW 1920
#define OH 540
#define OW 960
#define NIMG 24
#define XC 245           // staged cols: global -2..242 (local L = gcol+2)
#define XCP 248
#define NR 7             // staged rows 2B-2..2B+4 cover 8 output rows

typedef unsigned long long ull;

__device__ __forceinline__ ull f2pk(float lo, float hi) {
    ull r; asm("mov.b64 %0,{%1,%2};" : "=l"(r) : "f"(lo), "f"(hi)); return r;
}
__device__ __forceinline__ ull ffma2(ull a, ull b, ull c) {
    ull d; asm("fma.rn.f32x2 %0,%1,%2,%3;" : "=l"(d) : "l"(a), "l"(b), "l"(c)); return d;
}
__device__ __forceinline__ ull fadd2(ull a, ull b) {
    ull d; asm("add.rn.f32x2 %0,%1,%2;" : "=l"(d) : "l"(a), "l"(b)); return d;
}
__device__ __forceinline__ ull fmul2(ull a, ull b) {
    ull d; asm("mul.rn.f32x2 %0,%1,%2;" : "=l"(d) : "l"(a), "l"(b)); return d;
}
__device__ __forceinline__ void unpk2(float& lo, float& hi, ull v) {
    asm("mov.b64 {%0,%1},%2;" : "=f"(lo), "=f"(hi) : "l"(v));
}
// clip(trunc(v),0,255) as float, via saturating u8 convert (alu pipe)
__device__ __forceinline__ float finc(float v) {
    unsigned short t; asm("cvt.rzi.sat.u8.f32 %0,%1;" : "=h"(t) : "f"(v));
    float o;          asm("cvt.rn.f32.u8 %0,%1;" : "=f"(o) : "h"(t));
    return o;
}

// scalar horizontal 6-tap filters on window a..f (cols u-2..u+3)
#define HP1(a,b,c,d,e,f) fmaf(5.f,(a), fmaf(-18.f,(b), fmaf(114.f,(c), fmaf(36.f,(d), fmaf(-10.f,(e),(f))))))
#define HP2(a,b,c,d,e,f) fmaf(4.f,((a)+(f)), fmaf(-19.f,((b)+(e)), 79.f*((c)+(d))))
#define HP3(a,b,c,d,e,f) fmaf(5.f,(f), fmaf(-18.f,(e), fmaf(114.f,(d), fmaf(36.f,(c), fmaf(-10.f,(b),(a))))))

__global__ __launch_bounds__(240, 5)
void vtm_down_kernel(const float* __restrict__ x, float* __restrict__ out) {
    const int bc = blockIdx.y;            // image 0..23
    const int B  = blockIdx.x;            // 8-output-row band, 0..67

    __shared__ float xt[NR][XCP];

    const int tid = threadIdx.x;          // 0..239 : output-col tile
    const float* xim = x + (size_t)bc * (IH * IW);
    const int r0 = 2 * B - 2;

    // ---- stage 7 x 245 clamped input window ----
    const int c0 = tid - 2 < 0 ? 0 : tid - 2;
    #pragma unroll
    for (int r = 0; r < NR; r++) {
        int gr = r0 + r; if (gr < 0) gr = 0;
        const float* row = xim + (size_t)gr * IW;
        xt[r][tid] = __ldg(&row[c0]);
        if (tid < XC - 240) xt[r][240 + tid] = __ldg(&row[238 + tid]);
    }
    __syncthreads();

    // ---- horizontal 6-tap, 4 phases, packed (h0,h1) / (h2,h3) ----
    ull hA[NR], hB[NR];
    #pragma unroll
    for (int r = 0; r < NR; r++) {
        const float a = xt[r][tid];
        const float b = xt[r][tid + 1];
        const float c = xt[r][tid + 2];
        const float d = xt[r][tid + 3];
        const float e = xt[r][tid + 4];
        const float f = xt[r][tid + 5];
        hA[r] = f2pk(128.f * c,          HP1(a, b, c, d, e, f));
        hB[r] = f2pk(HP2(a, b, c, d, e, f), HP3(a, b, c, d, e, f));
    }

    // packed constants (hoisted by ptxas)
    const ull K5    = f2pk(5.f, 5.f),    Km18 = f2pk(-18.f, -18.f);
    const ull K114  = f2pk(114.f, 114.f), K36 = f2pk(36.f, 36.f);
    const ull Km10  = f2pk(-10.f, -10.f), K4  = f2pk(4.f, 4.f);
    const ull Km19  = f2pk(-19.f, -19.f), K79 = f2pk(79.f, 79.f);
    const ull K128  = f2pk(128.f, 128.f);
    const ull BIAS  = f2pk(8192.f, 8192.f);
    const ull KINV  = f2pk(6.103515625e-5f, 6.103515625e-5f);   // 2^-14

    float* oim = out + (size_t)bc * (OH * OW) + (size_t)(8 * B) * OW + tid * 4;

    #pragma unroll
    for (int bl = 0; bl < 2; bl++) {
        if (8 * B + 4 * bl < OH) {
            float* op = oim + (size_t)(4 * bl) * OW;
            float4 o;
            float lo, hi;

            // q = 0 : vertical delta
            {
                ull sA = ffma2(K128, hA[bl + 2], BIAS);
                ull sB = ffma2(K128, hB[bl + 2], BIAS);
                unpk2(lo, hi, fmul2(sA, KINV)); o.x = finc(lo); o.y = finc(hi);
                unpk2(lo, hi, fmul2(sB, KINV)); o.z = finc(lo); o.w = finc(hi);
                *(float4*)op = o;
            }
            // q = 1
            {
                ull sA = ffma2(K5, hA[bl], ffma2(Km18, hA[bl+1], ffma2(K114, hA[bl+2],
                         ffma2(K36, hA[bl+3], ffma2(Km10, hA[bl+4], fadd2(hA[bl+5], BIAS))))));
                ull sB = ffma2(K5, hB[bl], ffma2(Km18, hB[bl+1], ffma2(K114, hB[bl+2],
                         ffma2(K36, hB[bl+3], ffma2(Km10, hB[bl+4], fadd2(hB[bl+5], BIAS))))));
                unpk2(lo, hi, fmul2(sA, KINV)); o.x = finc(lo); o.y = finc(hi);
                unpk2(lo, hi, fmul2(sB, KINV)); o.z = finc(lo); o.w = finc(hi);
                *(float4*)(op + OW) = o;
            }
            // q = 2 : symmetric
            {
                ull sA = ffma2(K4, fadd2(hA[bl], hA[bl+5]),
                         ffma2(Km19, fadd2(hA[bl+1], hA[bl+4]),
                         ffma2(K79, fadd2(hA[bl+2], hA[bl+3]), BIAS)));
                ull sB = ffma2(K4, fadd2(hB[bl], hB[bl+5]),
                         ffma2(Km19, fadd2(hB[bl+1], hB[bl+4]),
                         ffma2(K79, fadd2(hB[bl+2], hB[bl+3]), BIAS)));
                unpk2(lo, hi, fmul2(sA, KINV)); o.x = finc(lo); o.y = finc(hi);
                unpk2(lo, hi, fmul2(sB, KINV)); o.z = finc(lo); o.w = finc(hi);
                *(float4*)(op + 2 * OW) = o;
            }
            // q = 3 : reversed q=1
            {
                ull sA = ffma2(K5, hA[bl+5], ffma2(Km18, hA[bl+4], ffma2(K114, hA[bl+3],
                         ffma2(K36, hA[bl+2], ffma2(Km10, hA[bl+1], fadd2(hA[bl], BIAS))))));
                ull sB = ffma2(K5, hB[bl+5], ffma2(Km18, hB[bl+4], ffma2(K114, hB[bl+3],
                         ffma2(K36, hB[bl+2], ffma2(Km10, hB[bl+1], fadd2(hB[bl], BIAS))))));
                unpk2(lo, hi, fmul2(sA, KINV)); o.x = finc(lo); o.y = finc(hi);
                unpk2(lo, hi, fmul2(sB, KINV)); o.z = finc(lo); o.w = finc(hi);
                *(float4*)(op + 3 * OW) = o;
            }
        }
    }
}

extern "C" void kernel_launch(void* const* d_in, const int* in_sizes, int n_in,
                              void* d_out, int out_size) {
    const float* x = (const float*)d_in[0];
    float* out = (float*)d_out;
    dim3 grid((OH + 7) / 8, NIMG);        // 68 x 24 = 1632 blocks
    vtm_down_kernel<<<grid, 240>>>(x, out);
}